// round 5
// baseline (speedup 1.0000x reference)
#include <cuda_runtime.h>
#include <cuda_bf16.h>

// Problem constants (match setup_inputs: P=1024, M=64, R=64)
#define P 1024
#define MDIM 64
#define RDIM 64
#define ROWS 4            // rows of the output handled per block
#define NBLK (P / ROWS)   // 256 blocks
#define NTHR 256

// Scratch for precomputed hi = H @ Wi, hj = H @ Wj (allocation-free: __device__ globals)
__device__ float g_hi[P];
__device__ float g_hj[P];

// ---------------------------------------------------------------------------
// Kernel 1: warp-per-row dot products  hi[i] = dot(H[i], W[64:128]),
//                                      hj[i] = dot(H[i], W[128:192])
// grid 128 x 256 threads = 1024 warps
// ---------------------------------------------------------------------------
__global__ __launch_bounds__(256) void precompute_kernel(
    const float* __restrict__ hidden, const float* __restrict__ W)
{
    int warp = threadIdx.x >> 5;
    int lane = threadIdx.x & 31;
    int row  = blockIdx.x * 8 + warp;

    float2 h = reinterpret_cast<const float2*>(hidden + (size_t)row * MDIM)[lane];
    float wi0 = W[RDIM + lane * 2];
    float wi1 = W[RDIM + lane * 2 + 1];
    float wj0 = W[RDIM + MDIM + lane * 2];
    float wj1 = W[RDIM + MDIM + lane * 2 + 1];

    float si = h.x * wi0 + h.y * wi1;
    float sj = h.x * wj0 + h.y * wj1;
    #pragma unroll
    for (int off = 16; off >= 1; off >>= 1) {
        si += __shfl_xor_sync(0xFFFFFFFFu, si, off);
        sj += __shfl_xor_sync(0xFFFFFFFFu, sj, off);
    }
    if (lane == 0) {
        g_hi[row] = si;
        g_hj[row] = sj;
    }
}

// ---------------------------------------------------------------------------
// Kernel 2: fused scores -> masked softmax -> attn @ hidden for ROWS rows/block
// ---------------------------------------------------------------------------
__global__ __launch_bounds__(NTHR) void social_main_kernel(
    const float* __restrict__ hidden,
    const float* __restrict__ rela,
    const int*   __restrict__ nei,
    const float* __restrict__ W,
    const float* __restrict__ bptr,
    float*       __restrict__ out)
{
    __shared__ float sWr[RDIM];            // W[0:64]
    __shared__ float sc[ROWS][P];          // scores -> exp -> attn (in place), 16 KB
    __shared__ float redmax[ROWS][8];
    __shared__ float redsum[ROWS][8];
    __shared__ float part[ROWS * 4][MDIM]; // [jg*ROWS + r][d] partials, 4 KB

    const int tid  = threadIdx.x;
    const int warp = tid >> 5;
    const int lane = tid & 31;
    const int half = (lane >> 4);          // 0/1 within warp
    const int lh   = lane & 15;            // lane within half-warp
    const int hwid = warp * 2 + half;      // 0..15 half-warp id

    if (tid < RDIM) sWr[tid] = W[tid];
    const float b = bptr[0];
    __syncthreads();

    const int i0 = blockIdx.x * ROWS;

    // ---- Phase 1: scores for ROWS rows ----
    const float4* wr4 = reinterpret_cast<const float4*>(sWr);
    const float4  wv  = wr4[lh];

    #pragma unroll
    for (int r = 0; r < ROWS; r++) {
        const int i = i0 + r;
        const float hii = g_hi[i];
        const float4* rp = reinterpret_cast<const float4*>(rela + (size_t)i * (P * RDIM));
        const int*    nrow = nei + (size_t)i * P;

        #pragma unroll 8
        for (int k = 0; k < P / 16; k++) {      // 16 j's per iteration (one per half-warp)
            const int j = k * 16 + hwid;
            float4 v = rp[(size_t)j * 16 + lh]; // 16 lanes x float4 = 256 B contiguous
            float s = v.x * wv.x + v.y * wv.y + v.z * wv.z + v.w * wv.w;
            // reduce within the 16-lane half (xor 1,2,4,8 stays inside the half)
            s += __shfl_xor_sync(0xFFFFFFFFu, s, 1);
            s += __shfl_xor_sync(0xFFFFFFFFu, s, 2);
            s += __shfl_xor_sync(0xFFFFFFFFu, s, 4);
            s += __shfl_xor_sync(0xFFFFFFFFu, s, 8);
            if (lh == 0) {
                float sc_full = s + hii + g_hj[j] + b;
                bool  m = nrow[j] > 0;
                float pos = m ? sc_full : 0.0f;
                if (pos == 0.0f) pos = -1e-6f;
                sc[r][j] = pos;
            }
        }
    }
    __syncthreads();

    // ---- Phase 2: softmax (full-row, then re-mask) ----
    float mx[ROWS];
    #pragma unroll
    for (int r = 0; r < ROWS; r++) mx[r] = -1e30f;
    for (int j = tid; j < P; j += NTHR) {
        #pragma unroll
        for (int r = 0; r < ROWS; r++) mx[r] = fmaxf(mx[r], sc[r][j]);
    }
    #pragma unroll
    for (int r = 0; r < ROWS; r++) {
        #pragma unroll
        for (int off = 16; off >= 1; off >>= 1)
            mx[r] = fmaxf(mx[r], __shfl_xor_sync(0xFFFFFFFFu, mx[r], off));
    }
    if (lane == 0) {
        #pragma unroll
        for (int r = 0; r < ROWS; r++) redmax[r][warp] = mx[r];
    }
    __syncthreads();
    float bmx[ROWS];
    #pragma unroll
    for (int r = 0; r < ROWS; r++) {
        float m = redmax[r][0];
        #pragma unroll
        for (int w = 1; w < 8; w++) m = fmaxf(m, redmax[r][w]);
        bmx[r] = m;
    }

    float sum[ROWS];
    #pragma unroll
    for (int r = 0; r < ROWS; r++) sum[r] = 0.0f;
    for (int j = tid; j < P; j += NTHR) {
        #pragma unroll
        for (int r = 0; r < ROWS; r++) {
            float e = __expf(sc[r][j] - bmx[r]);
            sc[r][j] = e;        // owner-thread in-place update, no hazard
            sum[r] += e;
        }
    }
    #pragma unroll
    for (int r = 0; r < ROWS; r++) {
        #pragma unroll
        for (int off = 16; off >= 1; off >>= 1)
            sum[r] += __shfl_xor_sync(0xFFFFFFFFu, sum[r], off);
    }
    if (lane == 0) {
        #pragma unroll
        for (int r = 0; r < ROWS; r++) redsum[r][warp] = sum[r];
    }
    __syncthreads();
    float inv[ROWS];
    #pragma unroll
    for (int r = 0; r < ROWS; r++) {
        float s = 0.0f;
        #pragma unroll
        for (int w = 0; w < 8; w++) s += redsum[r][w];
        inv[r] = 1.0f / s;
    }

    // attn = mask ? softmax : 0   (owner-thread in place)
    for (int j = tid; j < P; j += NTHR) {
        #pragma unroll
        for (int r = 0; r < ROWS; r++) {
            bool m = nei[(size_t)(i0 + r) * P + j] > 0;
            sc[r][j] = m ? (sc[r][j] * inv[r]) : 0.0f;
        }
    }
    __syncthreads();

    // ---- Phase 3: H_sum[i, d] = sum_j attn[i][j] * hidden[j][d] ----
    const int d  = tid & (MDIM - 1);
    const int jg = tid >> 6;   // 0..3
    float acc[ROWS];
    #pragma unroll
    for (int r = 0; r < ROWS; r++) acc[r] = 0.0f;

    #pragma unroll 4
    for (int j = jg; j < P; j += 4) {
        float h = hidden[(size_t)j * MDIM + d];   // block reads contiguous 1 KB/iter
        #pragma unroll
        for (int r = 0; r < ROWS; r++) acc[r] += sc[r][j] * h;  // broadcast LDS
    }
    #pragma unroll
    for (int r = 0; r < ROWS; r++) part[jg * ROWS + r][d] = acc[r];
    __syncthreads();

    // tid -> (r = tid/64, d = tid%64); sum the 4 jg partials and store
    {
        const int r2 = tid >> 6;
        const int d2 = tid & (MDIM - 1);
        float o = part[0 * ROWS + r2][d2] + part[1 * ROWS + r2][d2]
                + part[2 * ROWS + r2][d2] + part[3 * ROWS + r2][d2];
        out[(size_t)(i0 + r2) * MDIM + d2] = o;
    }
}

// ---------------------------------------------------------------------------
// Inputs (metadata order): 0 hidden_state f32[1024,64], 1 rela_state f32[1024,1024,64],
// 2 corr_index f32 (UNUSED), 3 nei_index i32[1024,1024], 4 W f32[192], 5 b f32[1].
// Output: f32[1024,64].
// ---------------------------------------------------------------------------
extern "C" void kernel_launch(void* const* d_in, const int* in_sizes, int n_in,
                              void* d_out, int out_size)
{
    const float* hidden = (const float*)d_in[0];
    const float* rela   = (const float*)d_in[1];
    const int*   nei    = (const int*)  d_in[3];
    const float* W      = (const float*)d_in[4];
    const float* b      = (const float*)d_in[5];
    float*       out    = (float*)d_out;

    precompute_kernel<<<P / 8, 256>>>(hidden, W);
    social_main_kernel<<<NBLK, NTHR>>>(hidden, rela, nei, W, b, out);
}

// round 6
// speedup vs baseline: 1.4551x; 1.4551x over previous
#include <cuda_runtime.h>
#include <cuda_bf16.h>

// Problem constants (match setup_inputs: P=1024, M=64, R=64)
#define P 1024
#define MDIM 64
#define RDIM 64
#define NTHR 256

// Scratch for precomputed hi = H @ Wi, hj = H @ Wj (allocation-free: __device__ globals)
__device__ float g_hi[P];
__device__ float g_hj[P];

// ---------------------------------------------------------------------------
// Kernel 1: warp-per-row dot products  hi[i] = dot(H[i], W[64:128]),
//                                      hj[i] = dot(H[i], W[128:192])
// ---------------------------------------------------------------------------
__global__ __launch_bounds__(256) void precompute_kernel(
    const float* __restrict__ hidden, const float* __restrict__ W)
{
    int warp = threadIdx.x >> 5;
    int lane = threadIdx.x & 31;
    int row  = blockIdx.x * 8 + warp;

    float2 h = reinterpret_cast<const float2*>(hidden + (size_t)row * MDIM)[lane];
    float wi0 = W[RDIM + lane * 2];
    float wi1 = W[RDIM + lane * 2 + 1];
    float wj0 = W[RDIM + MDIM + lane * 2];
    float wj1 = W[RDIM + MDIM + lane * 2 + 1];

    float si = h.x * wi0 + h.y * wi1;
    float sj = h.x * wj0 + h.y * wj1;
    #pragma unroll
    for (int off = 16; off >= 1; off >>= 1) {
        si += __shfl_xor_sync(0xFFFFFFFFu, si, off);
        sj += __shfl_xor_sync(0xFFFFFFFFu, sj, off);
    }
    if (lane == 0) {
        g_hi[row] = si;
        g_hj[row] = sj;
    }
}

// ---------------------------------------------------------------------------
// Kernel 2: one block per output row i. Fused:
//   scores -> masked "Pos" -> softmax (full row) -> re-mask -> attn @ hidden
// grid = 1024 -> ~7 CTAs/SM, enough in-flight LDGs to cover DRAM latency.
// ---------------------------------------------------------------------------
__global__ __launch_bounds__(NTHR) void social_main_kernel(
    const float* __restrict__ hidden,
    const float* __restrict__ rela,
    const int*   __restrict__ nei,
    const float* __restrict__ W,
    const float* __restrict__ bptr,
    float*       __restrict__ out)
{
    __shared__ float sWr[RDIM];       // W[0:64]
    __shared__ float sc[P];           // scores -> exp -> attn (in place), 4 KB
    __shared__ float red[8];
    __shared__ float part[4][MDIM];   // phase-3 partials, 1 KB

    const int tid  = threadIdx.x;
    const int warp = tid >> 5;
    const int lane = tid & 31;
    const int half = (lane >> 4);          // 0/1 within warp
    const int lh   = lane & 15;            // lane within half-warp
    const int hwid = warp * 2 + half;      // 0..15 half-warp id

    if (tid < RDIM) sWr[tid] = W[tid];
    const float b = bptr[0];
    __syncthreads();

    const int i = blockIdx.x;

    // ---- Phase 1: scores for row i (stream 256 KB of rela, coalesced) ----
    {
        const float4  wv  = reinterpret_cast<const float4*>(sWr)[lh];
        const float   hii = g_hi[i];
        const float4* rp  = reinterpret_cast<const float4*>(rela + (size_t)i * (P * RDIM));
        const int*    nrow = nei + (size_t)i * P;

        #pragma unroll 8
        for (int k = 0; k < P / 16; k++) {      // 16 j's per iteration (one per half-warp)
            const int j = k * 16 + hwid;
            float4 v = rp[(size_t)j * 16 + lh]; // 16 lanes x float4 = 256 B contiguous
            float s = v.x * wv.x + v.y * wv.y + v.z * wv.z + v.w * wv.w;
            // reduce within the 16-lane half (xor 1,2,4,8 stays inside the half)
            s += __shfl_xor_sync(0xFFFFFFFFu, s, 1);
            s += __shfl_xor_sync(0xFFFFFFFFu, s, 2);
            s += __shfl_xor_sync(0xFFFFFFFFu, s, 4);
            s += __shfl_xor_sync(0xFFFFFFFFu, s, 8);
            if (lh == 0) {
                float sc_full = s + hii + g_hj[j] + b;
                bool  m = nrow[j] > 0;
                float pos = m ? sc_full : 0.0f;
                if (pos == 0.0f) pos = -1e-6f;
                sc[j] = pos;
            }
        }
    }
    __syncthreads();

    // ---- Phase 2: softmax over full row, then re-mask ----
    float mx = -1e30f;
    #pragma unroll
    for (int k = 0; k < P / NTHR; k++) mx = fmaxf(mx, sc[k * NTHR + tid]);
    #pragma unroll
    for (int off = 16; off >= 1; off >>= 1)
        mx = fmaxf(mx, __shfl_xor_sync(0xFFFFFFFFu, mx, off));
    if (lane == 0) red[warp] = mx;
    __syncthreads();
    {
        float m = red[0];
        #pragma unroll
        for (int w = 1; w < 8; w++) m = fmaxf(m, red[w]);
        mx = m;
    }
    __syncthreads();   // red[] reuse safety before sum phase writes

    float sum = 0.0f;
    #pragma unroll
    for (int k = 0; k < P / NTHR; k++) {
        int j = k * NTHR + tid;
        float e = __expf(sc[j] - mx);
        sc[j] = e;                 // owner-thread in-place, no hazard
        sum += e;
    }
    #pragma unroll
    for (int off = 16; off >= 1; off >>= 1)
        sum += __shfl_xor_sync(0xFFFFFFFFu, sum, off);
    if (lane == 0) red[warp] = sum;
    __syncthreads();
    float inv;
    {
        float s = 0.0f;
        #pragma unroll
        for (int w = 0; w < 8; w++) s += red[w];
        inv = 1.0f / s;
    }

    // attn = mask ? softmax/sum : 0  (nei row is an L2 hit: 4 KB, re-read)
    #pragma unroll
    for (int k = 0; k < P / NTHR; k++) {
        int j = k * NTHR + tid;
        bool m = nei[(size_t)i * P + j] > 0;
        sc[j] = m ? (sc[j] * inv) : 0.0f;
    }
    __syncthreads();

    // ---- Phase 3: H_sum[i, d] = sum_j attn[j] * hidden[j][d] ----
    // thread = (d = tid&63, jg = tid>>6); hidden rows stream from L1/L2.
    const int d  = tid & (MDIM - 1);
    const int jg = tid >> 6;   // 0..3
    float acc = 0.0f;
    #pragma unroll 8
    for (int j = jg; j < P; j += 4) {
        acc += sc[j] * hidden[(size_t)j * MDIM + d];  // coalesced per jg-group
    }
    part[jg][d] = acc;
    __syncthreads();

    if (tid < MDIM) {
        float o = part[0][tid] + part[1][tid] + part[2][tid] + part[3][tid];
        out[(size_t)i * MDIM + tid] = o;
    }
}

// ---------------------------------------------------------------------------
// Inputs (metadata order): 0 hidden_state f32[1024,64], 1 rela_state f32[1024,1024,64],
// 2 corr_index f32 (UNUSED), 3 nei_index i32[1024,1024], 4 W f32[192], 5 b f32[1].
// Output: f32[1024,64].
// ---------------------------------------------------------------------------
extern "C" void kernel_launch(void* const* d_in, const int* in_sizes, int n_in,
                              void* d_out, int out_size)
{
    const float* hidden = (const float*)d_in[0];
    const float* rela   = (const float*)d_in[1];
    const int*   nei    = (const int*)  d_in[3];
    const float* W      = (const float*)d_in[4];
    const float* b      = (const float*)d_in[5];
    float*       out    = (float*)d_out;

    precompute_kernel<<<P / 8, 256>>>(hidden, W);
    social_main_kernel<<<P, NTHR>>>(hidden, rela, nei, W, b, out);
}

// round 7
// speedup vs baseline: 1.5394x; 1.0579x over previous
#include <cuda_runtime.h>
#include <cuda_bf16.h>

// Problem constants (match setup_inputs: P=1024, M=64, R=64)
#define P 1024
#define MDIM 64
#define RDIM 64
#define NTHR 256
#define BROWS 4   // rows per block in the H_sum kernel

// Allocation-free scratch (__device__ globals)
__device__ float g_hi[P];
__device__ float g_hj[P];
__device__ float g_attn[P * P];   // 4 MB: final masked+normalized attention

// ---------------------------------------------------------------------------
// Kernel 1: warp-per-row dot products  hi[i] = dot(H[i], W[64:128]),
//                                      hj[i] = dot(H[i], W[128:192])
// ---------------------------------------------------------------------------
__global__ __launch_bounds__(256) void precompute_kernel(
    const float* __restrict__ hidden, const float* __restrict__ W)
{
    int warp = threadIdx.x >> 5;
    int lane = threadIdx.x & 31;
    int row  = blockIdx.x * 8 + warp;

    float2 h = reinterpret_cast<const float2*>(hidden + (size_t)row * MDIM)[lane];
    float wi0 = W[RDIM + lane * 2];
    float wi1 = W[RDIM + lane * 2 + 1];
    float wj0 = W[RDIM + MDIM + lane * 2];
    float wj1 = W[RDIM + MDIM + lane * 2 + 1];

    float si = h.x * wi0 + h.y * wi1;
    float sj = h.x * wj0 + h.y * wj1;
    #pragma unroll
    for (int off = 16; off >= 1; off >>= 1) {
        si += __shfl_xor_sync(0xFFFFFFFFu, si, off);
        sj += __shfl_xor_sync(0xFFFFFFFFu, sj, off);
    }
    if (lane == 0) {
        g_hi[row] = si;
        g_hj[row] = sj;
    }
}

// ---------------------------------------------------------------------------
// Kernel 2 (Kernel A): one block per row i.
//   scores (256 KB DRAM stream) -> masked "Pos" -> softmax -> re-mask
//   -> write attn row to g_attn. NO hidden re-read here: warps stream DRAM
//   for essentially their whole lifetime.
// ---------------------------------------------------------------------------
__global__ __launch_bounds__(NTHR) void scores_softmax_kernel(
    const float* __restrict__ rela,
    const int*   __restrict__ nei,
    const float* __restrict__ W,
    const float* __restrict__ bptr)
{
    __shared__ float sWr[RDIM];          // W[0:64]
    __shared__ float shj[P];             // g_hj staged (4 KB)
    __shared__ float sc[P];              // scores -> exp (4 KB)
    __shared__ unsigned char smask[P];   // nei>0 (1 KB)
    __shared__ float red[8];

    const int tid  = threadIdx.x;
    const int warp = tid >> 5;
    const int lane = tid & 31;
    const int half = (lane >> 4);
    const int lh   = lane & 15;          // lane within half-warp
    const int hwid = warp * 2 + half;    // 0..15 half-warp id

    const int i = blockIdx.x;

    if (tid < RDIM) sWr[tid] = W[tid];
    // stage hj (float4) and mask (packed 4 bytes per thread)
    reinterpret_cast<float4*>(shj)[tid] = reinterpret_cast<const float4*>(g_hj)[tid];
    {
        int4 n4 = reinterpret_cast<const int4*>(nei + (size_t)i * P)[tid];
        unsigned int m = (n4.x > 0 ? 1u : 0u) | (n4.y > 0 ? 0x100u : 0u)
                       | (n4.z > 0 ? 0x10000u : 0u) | (n4.w > 0 ? 0x1000000u : 0u);
        reinterpret_cast<unsigned int*>(smask)[tid] = m;
    }
    const float b = bptr[0];
    __syncthreads();

    // ---- Phase 1: scores for row i (stream 256 KB of rela, coalesced) ----
    {
        const float4  wv  = reinterpret_cast<const float4*>(sWr)[lh];
        const float   hii = g_hi[i];
        const float4* rp  = reinterpret_cast<const float4*>(rela + (size_t)i * (P * RDIM));

        #pragma unroll 8
        for (int k = 0; k < P / 16; k++) {      // 16 j's per iteration
            const int j = k * 16 + hwid;
            float4 v = rp[(size_t)j * 16 + lh]; // 16 lanes x float4 = 256 B contiguous
            float s = v.x * wv.x + v.y * wv.y + v.z * wv.z + v.w * wv.w;
            s += __shfl_xor_sync(0xFFFFFFFFu, s, 1);
            s += __shfl_xor_sync(0xFFFFFFFFu, s, 2);
            s += __shfl_xor_sync(0xFFFFFFFFu, s, 4);
            s += __shfl_xor_sync(0xFFFFFFFFu, s, 8);
            if (lh == 0) {
                float sc_full = s + hii + shj[j] + b;
                float pos = smask[j] ? sc_full : 0.0f;
                if (pos == 0.0f) pos = -1e-6f;
                sc[j] = pos;
            }
        }
    }
    __syncthreads();

    // ---- Phase 2: softmax over full row ----
    float mx = -1e30f;
    #pragma unroll
    for (int k = 0; k < P / NTHR; k++) mx = fmaxf(mx, sc[k * NTHR + tid]);
    #pragma unroll
    for (int off = 16; off >= 1; off >>= 1)
        mx = fmaxf(mx, __shfl_xor_sync(0xFFFFFFFFu, mx, off));
    if (lane == 0) red[warp] = mx;
    __syncthreads();
    {
        float m = red[0];
        #pragma unroll
        for (int w = 1; w < 8; w++) m = fmaxf(m, red[w]);
        mx = m;
    }
    __syncthreads();

    float sum = 0.0f;
    #pragma unroll
    for (int k = 0; k < P / NTHR; k++) {
        int j = k * NTHR + tid;
        float e = __expf(sc[j] - mx);
        sc[j] = e;
        sum += e;
    }
    #pragma unroll
    for (int off = 16; off >= 1; off >>= 1)
        sum += __shfl_xor_sync(0xFFFFFFFFu, sum, off);
    if (lane == 0) red[warp] = sum;
    __syncthreads();
    float inv;
    {
        float s = 0.0f;
        #pragma unroll
        for (int w = 0; w < 8; w++) s += red[w];
        inv = 1.0f / s;
    }

    // ---- write final attn row (masked, normalized) as float4 ----
    {
        float4 a;
        int j0 = tid * 4;
        a.x = smask[j0 + 0] ? sc[j0 + 0] * inv : 0.0f;
        a.y = smask[j0 + 1] ? sc[j0 + 1] * inv : 0.0f;
        a.z = smask[j0 + 2] ? sc[j0 + 2] * inv : 0.0f;
        a.w = smask[j0 + 3] ? sc[j0 + 3] * inv : 0.0f;
        reinterpret_cast<float4*>(g_attn + (size_t)i * P)[tid] = a;
    }
}

// ---------------------------------------------------------------------------
// Kernel 3 (Kernel B): H_sum = attn @ hidden.  4 rows per block, 256 blocks.
// attn rows staged in smem; 4 independent accumulators break the FFMA chain;
// hidden read once per block (L2 hits), coalesced per jg-group.
// ---------------------------------------------------------------------------
__global__ __launch_bounds__(NTHR) void hsum_kernel(
    const float* __restrict__ hidden,
    float*       __restrict__ out)
{
    __shared__ float sat[BROWS][P];        // 16 KB
    __shared__ float part[4][BROWS][MDIM]; // 4 KB

    const int tid = threadIdx.x;
    const int i0  = blockIdx.x * BROWS;

    #pragma unroll
    for (int r = 0; r < BROWS; r++)
        reinterpret_cast<float4*>(sat[r])[tid] =
            reinterpret_cast<const float4*>(g_attn + (size_t)(i0 + r) * P)[tid];
    __syncthreads();

    const int d  = tid & (MDIM - 1);
    const int jg = tid >> 6;   // 0..3
    float acc[BROWS];
    #pragma unroll
    for (int r = 0; r < BROWS; r++) acc[r] = 0.0f;

    #pragma unroll 8
    for (int j = jg; j < P; j += 4) {
        float h = hidden[(size_t)j * MDIM + d];   // contiguous 256 B per jg-group
        #pragma unroll
        for (int r = 0; r < BROWS; r++) acc[r] += sat[r][j] * h;
    }
    #pragma unroll
    for (int r = 0; r < BROWS; r++) part[jg][r][d] = acc[r];
    __syncthreads();

    {
        const int r2 = tid >> 6;          // BROWS=4 -> exactly 256 threads
        const int d2 = tid & (MDIM - 1);
        float o = part[0][r2][d2] + part[1][r2][d2]
                + part[2][r2][d2] + part[3][r2][d2];
        out[(size_t)(i0 + r2) * MDIM + d2] = o;
    }
}

// ---------------------------------------------------------------------------
// Inputs (metadata order): 0 hidden_state f32[1024,64], 1 rela_state f32[1024,1024,64],
// 2 corr_index f32 (UNUSED), 3 nei_index i32[1024,1024], 4 W f32[192], 5 b f32[1].
// Output: f32[1024,64].
// ---------------------------------------------------------------------------
extern "C" void kernel_launch(void* const* d_in, const int* in_sizes, int n_in,
                              void* d_out, int out_size)
{
    const float* hidden = (const float*)d_in[0];
    const float* rela   = (const float*)d_in[1];
    const int*   nei    = (const int*)  d_in[3];
    const float* W      = (const float*)d_in[4];
    const float* b      = (const float*)d_in[5];
    float*       out    = (float*)d_out;

    precompute_kernel<<<P / 8, 256>>>(hidden, W);
    scores_softmax_kernel<<<P, NTHR>>>(rela, nei, W, b);
    hsum_kernel<<<P / BROWS, NTHR>>>(hidden, out);
}

// round 8
// speedup vs baseline: 1.9045x; 1.2372x over previous
#include <cuda_runtime.h>
#include <cuda_bf16.h>

// Problem constants (match setup_inputs: P=1024, M=64, R=64)
#define P 1024
#define MDIM 64
#define RDIM 64
#define NTHR 256
#define BROWS 4   // rows per block in the H_sum kernel
#define PF 4      // software-pipeline depth (float4 buffers in flight)

// Allocation-free scratch (__device__ globals)
__device__ float g_hi[P];
__device__ float g_hj[P];
__device__ float g_attn[P * P];   // 4 MB: final masked+normalized attention

// ---------------------------------------------------------------------------
// Kernel 1: warp-per-row dot products  hi[i] = dot(H[i], W[64:128]),
//                                      hj[i] = dot(H[i], W[128:192])
// ---------------------------------------------------------------------------
__global__ __launch_bounds__(256) void precompute_kernel(
    const float* __restrict__ hidden, const float* __restrict__ W)
{
    int warp = threadIdx.x >> 5;
    int lane = threadIdx.x & 31;
    int row  = blockIdx.x * 8 + warp;

    float2 h = reinterpret_cast<const float2*>(hidden + (size_t)row * MDIM)[lane];
    float wi0 = W[RDIM + lane * 2];
    float wi1 = W[RDIM + lane * 2 + 1];
    float wj0 = W[RDIM + MDIM + lane * 2];
    float wj1 = W[RDIM + MDIM + lane * 2 + 1];

    float si = h.x * wi0 + h.y * wi1;
    float sj = h.x * wj0 + h.y * wj1;
    #pragma unroll
    for (int off = 16; off >= 1; off >>= 1) {
        si += __shfl_xor_sync(0xFFFFFFFFu, si, off);
        sj += __shfl_xor_sync(0xFFFFFFFFu, sj, off);
    }
    if (lane == 0) {
        g_hi[row] = si;
        g_hj[row] = sj;
    }
}

// ---------------------------------------------------------------------------
// Kernel 2 (Kernel A): one block per row i.
// Phase 1 streams 256 KB of rela with a depth-4 software pipeline and only
// ONE shfl per float4 (partials spilled to padded smem). Phase 2 finishes the
// dot, applies mask/bias, softmax, re-mask, writes attn row to g_attn.
// ---------------------------------------------------------------------------
__global__ __launch_bounds__(NTHR) void scores_softmax_kernel(
    const float* __restrict__ rela,
    const int*   __restrict__ nei,
    const float* __restrict__ W,
    const float* __restrict__ bptr)
{
    __shared__ float part[P * 9];        // 8 partials per j, padded to 9 (36 KB)
    __shared__ float shj[P];             // g_hj staged (4 KB)
    __shared__ float sc[P];              // pos -> exp (4 KB)
    __shared__ unsigned char smask[P];   // nei>0 (1 KB)
    __shared__ float sWr[RDIM];
    __shared__ float red[8];

    const int tid  = threadIdx.x;
    const int warp = tid >> 5;
    const int lane = tid & 31;
    const int half = (lane >> 4);
    const int lh   = lane & 15;          // lane within half-warp
    const int hwid = warp * 2 + half;    // 0..15 half-warp id

    const int i = blockIdx.x;

    if (tid < RDIM) sWr[tid] = W[tid];
    reinterpret_cast<float4*>(shj)[tid] = reinterpret_cast<const float4*>(g_hj)[tid];
    {
        int4 n4 = reinterpret_cast<const int4*>(nei + (size_t)i * P)[tid];
        unsigned int m = (n4.x > 0 ? 1u : 0u) | (n4.y > 0 ? 0x100u : 0u)
                       | (n4.z > 0 ? 0x10000u : 0u) | (n4.w > 0 ? 0x1000000u : 0u);
        reinterpret_cast<unsigned int*>(smask)[tid] = m;
    }
    const float b   = bptr[0];
    const float hii = g_hi[i];
    __syncthreads();

    // ---- Phase 1: stream rela row i, depth-4 pipelined, 1 shfl per float4 ----
    {
        const float4 wv = reinterpret_cast<const float4*>(sWr)[lh];
        // iteration k handles j = k*16 + hwid; this thread reads float4 #lh of j
        const float4* p = reinterpret_cast<const float4*>(rela + (size_t)i * (P * RDIM))
                        + (size_t)hwid * 16 + lh;
        // stride between consecutive k for this thread: 16 j's * 16 float4 = 256
        float4 buf[PF];
        #pragma unroll
        for (int q = 0; q < PF; q++) buf[q] = p[q * 256];
        p += PF * 256;

        #pragma unroll 4
        for (int kk = 0; kk < 64 / PF; kk++) {
            #pragma unroll
            for (int q = 0; q < PF; q++) {
                float4 v = buf[q];
                if (kk < 64 / PF - 1) buf[q] = p[q * 256];   // prefetch k+PF
                float s = fmaf(v.x, wv.x, fmaf(v.y, wv.y, fmaf(v.z, wv.z, v.w * wv.w)));
                s += __shfl_xor_sync(0xFFFFFFFFu, s, 8);     // fold 16 lanes -> 8 partials
                const int j = (kk * PF + q) * 16 + hwid;
                if (lh < 8) part[j * 9 + lh] = s;
            }
            p += PF * 256;
        }
    }
    __syncthreads();

    // ---- Phase 2a: finish dots + bias + mask + "Pos", fused with max-pass ----
    float mx = -1e30f;
    #pragma unroll
    for (int q = 0; q < P / NTHR; q++) {
        const int j = q * NTHR + tid;            // lane stride 9 floats: conflict-free
        const float* pj = &part[j * 9];
        float s = ((pj[0] + pj[1]) + (pj[2] + pj[3]))
                + ((pj[4] + pj[5]) + (pj[6] + pj[7]));
        s += hii + shj[j] + b;
        float pos = smask[j] ? s : 0.0f;
        if (pos == 0.0f) pos = -1e-6f;
        sc[j] = pos;
        mx = fmaxf(mx, pos);
    }
    #pragma unroll
    for (int off = 16; off >= 1; off >>= 1)
        mx = fmaxf(mx, __shfl_xor_sync(0xFFFFFFFFu, mx, off));
    if (lane == 0) red[warp] = mx;
    __syncthreads();
    {
        float m = red[0];
        #pragma unroll
        for (int w = 1; w < 8; w++) m = fmaxf(m, red[w]);
        mx = m;
    }
    __syncthreads();

    // ---- Phase 2b: exp + sum ----
    float sum = 0.0f;
    #pragma unroll
    for (int q = 0; q < P / NTHR; q++) {
        int j = q * NTHR + tid;
        float e = __expf(sc[j] - mx);
        sc[j] = e;
        sum += e;
    }
    #pragma unroll
    for (int off = 16; off >= 1; off >>= 1)
        sum += __shfl_xor_sync(0xFFFFFFFFu, sum, off);
    if (lane == 0) red[warp] = sum;
    __syncthreads();
    float inv;
    {
        float s = 0.0f;
        #pragma unroll
        for (int w = 0; w < 8; w++) s += red[w];
        inv = 1.0f / s;
    }

    // ---- write final attn row (masked, normalized) as float4 ----
    {
        float4 a;
        int j0 = tid * 4;
        a.x = smask[j0 + 0] ? sc[j0 + 0] * inv : 0.0f;
        a.y = smask[j0 + 1] ? sc[j0 + 1] * inv : 0.0f;
        a.z = smask[j0 + 2] ? sc[j0 + 2] * inv : 0.0f;
        a.w = smask[j0 + 3] ? sc[j0 + 3] * inv : 0.0f;
        reinterpret_cast<float4*>(g_attn + (size_t)i * P)[tid] = a;
    }
}

// ---------------------------------------------------------------------------
// Kernel 3 (Kernel B): H_sum = attn @ hidden.  4 rows per block, 256 blocks.
// ---------------------------------------------------------------------------
__global__ __launch_bounds__(NTHR) void hsum_kernel(
    const float* __restrict__ hidden,
    float*       __restrict__ out)
{
    __shared__ float sat[BROWS][P];        // 16 KB
    __shared__ float partb[4][BROWS][MDIM];

    const int tid = threadIdx.x;
    const int i0  = blockIdx.x * BROWS;

    #pragma unroll
    for (int r = 0; r < BROWS; r++)
        reinterpret_cast<float4*>(sat[r])[tid] =
            reinterpret_cast<const float4*>(g_attn + (size_t)(i0 + r) * P)[tid];
    __syncthreads();

    const int d  = tid & (MDIM - 1);
    const int jg = tid >> 6;   // 0..3
    float acc[BROWS];
    #pragma unroll
    for (int r = 0; r < BROWS; r++) acc[r] = 0.0f;

    #pragma unroll 8
    for (int j = jg; j < P; j += 4) {
        float h = hidden[(size_t)j * MDIM + d];   // contiguous per jg-group, L2 hits
        #pragma unroll
        for (int r = 0; r < BROWS; r++) acc[r] = fmaf(sat[r][j], h, acc[r]);
    }
    #pragma unroll
    for (int r = 0; r < BROWS; r++) partb[jg][r][d] = acc[r];
    __syncthreads();

    {
        const int r2 = tid >> 6;
        const int d2 = tid & (MDIM - 1);
        float o = partb[0][r2][d2] + partb[1][r2][d2]
                + partb[2][r2][d2] + partb[3][r2][d2];
        out[(size_t)(i0 + r2) * MDIM + d2] = o;
    }
}

// ---------------------------------------------------------------------------
// Inputs (metadata order): 0 hidden_state f32[1024,64], 1 rela_state f32[1024,1024,64],
// 2 corr_index f32 (UNUSED), 3 nei_index i32[1024,1024], 4 W f32[192], 5 b f32[1].
// Output: f32[1024,64].
// ---------------------------------------------------------------------------
extern "C" void kernel_launch(void* const* d_in, const int* in_sizes, int n_in,
                              void* d_out, int out_size)
{
    const float* hidden = (const float*)d_in[0];
    const float* rela   = (const float*)d_in[1];
    const int*   nei    = (const int*)  d_in[3];
    const float* W      = (const float*)d_in[4];
    const float* b      = (const float*)d_in[5];
    float*       out    = (float*)d_out;

    precompute_kernel<<<P / 8, 256>>>(hidden, W);
    scores_softmax_kernel<<<P, NTHR>>>(rela, nei, W, b);
    hsum_kernel<<<P / BROWS, NTHR>>>(hidden, out);
}

// round 9
// speedup vs baseline: 2.2931x; 1.2041x over previous
#include <cuda_runtime.h>
#include <cuda_bf16.h>

// Problem constants (match setup_inputs: P=1024, M=64, R=64)
#define P 1024
#define MDIM 64
#define RDIM 64
#define NTHR 256
#define PF 2       // software-pipeline depth (float4 buffers in flight)

// hsum tiling
#define ITILE 16
#define JTILE 128
#define NJT   (P / JTILE)   // 8
#define NIT   (P / ITILE)   // 64

// Allocation-free scratch (__device__ globals)
__device__ float g_hi[P];
__device__ float g_hj[P];
__device__ float g_attn[P * P];   // 4 MB: final masked+normalized attention

// ---------------------------------------------------------------------------
// Kernel 1: hi[i] = dot(H[i], W[64:128]), hj[i] = dot(H[i], W[128:192])
// Also zero-initializes d_out (65536 floats) so hsum can use atomicAdd.
// ---------------------------------------------------------------------------
__global__ __launch_bounds__(256) void precompute_kernel(
    const float* __restrict__ hidden, const float* __restrict__ W,
    float* __restrict__ out)
{
    int warp = threadIdx.x >> 5;
    int lane = threadIdx.x & 31;
    int row  = blockIdx.x * 8 + warp;
    int gid  = blockIdx.x * 256 + threadIdx.x;   // 32768 threads

    // zero d_out: 65536 floats = 32768 float2
    reinterpret_cast<float2*>(out)[gid] = make_float2(0.0f, 0.0f);

    float2 h = reinterpret_cast<const float2*>(hidden + (size_t)row * MDIM)[lane];
    float wi0 = W[RDIM + lane * 2];
    float wi1 = W[RDIM + lane * 2 + 1];
    float wj0 = W[RDIM + MDIM + lane * 2];
    float wj1 = W[RDIM + MDIM + lane * 2 + 1];

    float si = h.x * wi0 + h.y * wi1;
    float sj = h.x * wj0 + h.y * wj1;
    #pragma unroll
    for (int off = 16; off >= 1; off >>= 1) {
        si += __shfl_xor_sync(0xFFFFFFFFu, si, off);
        sj += __shfl_xor_sync(0xFFFFFFFFu, sj, off);
    }
    if (lane == 0) {
        g_hi[row] = si;
        g_hj[row] = sj;
    }
}

// ---------------------------------------------------------------------------
// Kernel 2: one block per row i. Streams 256 KB of rela (depth-2 pipeline),
// two shfl folds -> 4 partials/j in padded smem; finish + softmax + mask;
// writes attn row to g_attn.  smem ~29.5 KB -> 7 CTA/SM -> single wave.
// ---------------------------------------------------------------------------
__global__ __launch_bounds__(NTHR, 7) void scores_softmax_kernel(
    const float* __restrict__ rela,
    const int*   __restrict__ nei,
    const float* __restrict__ W,
    const float* __restrict__ bptr)
{
    __shared__ float part[P * 5];        // 4 partials per j, padded to 5 (20 KB)
    __shared__ float shj[P];             // g_hj staged (4 KB)
    __shared__ float sc[P];              // pos -> exp (4 KB)
    __shared__ unsigned char smask[P];   // nei>0 (1 KB)
    __shared__ float sWr[RDIM];
    __shared__ float red[8];

    const int tid  = threadIdx.x;
    const int warp = tid >> 5;
    const int lane = tid & 31;
    const int half = (lane >> 4);
    const int lh   = lane & 15;          // lane within half-warp
    const int hwid = warp * 2 + half;    // 0..15 half-warp id

    const int i = blockIdx.x;

    if (tid < RDIM) sWr[tid] = W[tid];
    reinterpret_cast<float4*>(shj)[tid] = reinterpret_cast<const float4*>(g_hj)[tid];
    {
        int4 n4 = reinterpret_cast<const int4*>(nei + (size_t)i * P)[tid];
        unsigned int m = (n4.x > 0 ? 1u : 0u) | (n4.y > 0 ? 0x100u : 0u)
                       | (n4.z > 0 ? 0x10000u : 0u) | (n4.w > 0 ? 0x1000000u : 0u);
        reinterpret_cast<unsigned int*>(smask)[tid] = m;
    }
    const float b   = bptr[0];
    const float hii = g_hi[i];
    __syncthreads();

    // ---- Phase 1: stream rela row i; 2 shfl folds -> 4 partials per j ----
    {
        const float4 wv = reinterpret_cast<const float4*>(sWr)[lh];
        // iteration k handles j = k*16 + hwid; this thread reads float4 #lh of j
        const float4* p = reinterpret_cast<const float4*>(rela + (size_t)i * (P * RDIM))
                        + (size_t)hwid * 16 + lh;
        // stride between consecutive k for this thread: 16 j's * 16 float4 = 256
        float4 buf[PF];
        #pragma unroll
        for (int q = 0; q < PF; q++) buf[q] = p[q * 256];
        p += PF * 256;

        #pragma unroll 8
        for (int kk = 0; kk < 64 / PF; kk++) {
            #pragma unroll
            for (int q = 0; q < PF; q++) {
                float4 v = buf[q];
                if (kk < 64 / PF - 1) buf[q] = p[q * 256];   // prefetch k+PF
                float s = fmaf(v.x, wv.x, fmaf(v.y, wv.y, fmaf(v.z, wv.z, v.w * wv.w)));
                s += __shfl_xor_sync(0xFFFFFFFFu, s, 8);     // 16 -> 8
                s += __shfl_xor_sync(0xFFFFFFFFu, s, 4);     // 8 -> 4 partials
                const int j = (kk * PF + q) * 16 + hwid;
                if (lh < 4) part[j * 5 + lh] = s;            // conflict-free (pad 5)
            }
            p += PF * 256;
        }
    }
    __syncthreads();

    // ---- Phase 2a: finish dots + bias + mask + "Pos", fused with max-pass ----
    float mx = -1e30f;
    #pragma unroll
    for (int q = 0; q < P / NTHR; q++) {
        const int j = q * NTHR + tid;            // lane stride 5 floats: conflict-free
        const float* pj = &part[j * 5];
        float s = (pj[0] + pj[1]) + (pj[2] + pj[3]);
        s += hii + shj[j] + b;
        float pos = smask[j] ? s : 0.0f;
        if (pos == 0.0f) pos = -1e-6f;
        sc[j] = pos;
        mx = fmaxf(mx, pos);
    }
    #pragma unroll
    for (int off = 16; off >= 1; off >>= 1)
        mx = fmaxf(mx, __shfl_xor_sync(0xFFFFFFFFu, mx, off));
    if (lane == 0) red[warp] = mx;
    __syncthreads();
    {
        float m = red[0];
        #pragma unroll
        for (int w = 1; w < 8; w++) m = fmaxf(m, red[w]);
        mx = m;
    }
    __syncthreads();

    // ---- Phase 2b: exp + sum ----
    float sum = 0.0f;
    #pragma unroll
    for (int q = 0; q < P / NTHR; q++) {
        int j = q * NTHR + tid;
        float e = __expf(sc[j] - mx);
        sc[j] = e;
        sum += e;
    }
    #pragma unroll
    for (int off = 16; off >= 1; off >>= 1)
        sum += __shfl_xor_sync(0xFFFFFFFFu, sum, off);
    if (lane == 0) red[warp] = sum;
    __syncthreads();
    float inv;
    {
        float s = 0.0f;
        #pragma unroll
        for (int w = 0; w < 8; w++) s += red[w];
        inv = 1.0f / s;
    }

    // ---- write final attn row (masked, normalized) as float4 ----
    {
        float4 a;
        int j0 = tid * 4;
        a.x = smask[j0 + 0] ? sc[j0 + 0] * inv : 0.0f;
        a.y = smask[j0 + 1] ? sc[j0 + 1] * inv : 0.0f;
        a.z = smask[j0 + 2] ? sc[j0 + 2] * inv : 0.0f;
        a.w = smask[j0 + 3] ? sc[j0 + 3] * inv : 0.0f;
        reinterpret_cast<float4*>(g_attn + (size_t)i * P)[tid] = a;
    }
}

// ---------------------------------------------------------------------------
// Kernel 3: H_sum = attn @ hidden, tiled: 64 i-tiles (16 rows) x 8 j-tiles
// (128 j) = 512 blocks. attn tile in smem, 16 accumulators/thread,
// jg-reduce in smem, atomicAdd to out (8 contributions per element).
// ---------------------------------------------------------------------------
__global__ __launch_bounds__(NTHR) void hsum_kernel(
    const float* __restrict__ hidden,
    float*       __restrict__ out)
{
    __shared__ float sat[ITILE][JTILE];          // 8 KB
    __shared__ float partb[4][ITILE][MDIM];      // 16 KB

    const int tid = threadIdx.x;
    const int it  = blockIdx.x >> 3;         // 0..63
    const int jt  = blockIdx.x & 7;          // 0..7
    const int i0  = it * ITILE;
    const int j0  = jt * JTILE;

    // stage attn tile: 512 float4, 2 per thread, coalesced
    #pragma unroll
    for (int t = tid; t < ITILE * JTILE / 4; t += NTHR) {
        int r  = t >> 5;                      // 32 float4 per row
        int c4 = t & 31;
        reinterpret_cast<float4*>(sat[r])[c4] =
            reinterpret_cast<const float4*>(g_attn + (size_t)(i0 + r) * P + j0)[c4];
    }
    __syncthreads();

    const int d  = tid & (MDIM - 1);
    const int jg = tid >> 6;                  // 0..3, 32 j's each
    float acc[ITILE];
    #pragma unroll
    for (int r = 0; r < ITILE; r++) acc[r] = 0.0f;

    #pragma unroll 4
    for (int jj = 0; jj < JTILE / 4; jj++) {
        int j = jg * (JTILE / 4) + jj;
        float h = hidden[(size_t)(j0 + j) * MDIM + d];   // coalesced, L2/L1 hits
        #pragma unroll
        for (int r = 0; r < ITILE; r++) acc[r] = fmaf(sat[r][j], h, acc[r]);
    }
    #pragma unroll
    for (int r = 0; r < ITILE; r++) partb[jg][r][d] = acc[r];
    __syncthreads();

    // each thread finalizes 4 (r,d) outputs
    #pragma unroll
    for (int rr = 0; rr < 4; rr++) {
        int r = rr * 4 + jg;
        float v = partb[0][r][d] + partb[1][r][d] + partb[2][r][d] + partb[3][r][d];
        atomicAdd(&out[(size_t)(i0 + r) * MDIM + d], v);
    }
}

// ---------------------------------------------------------------------------
// Inputs (metadata order): 0 hidden_state f32[1024,64], 1 rela_state f32[1024,1024,64],
// 2 corr_index f32 (UNUSED), 3 nei_index i32[1024,1024], 4 W f32[192], 5 b f32[1].
// Output: f32[1024,64].
// ---------------------------------------------------------------------------
extern "C" void kernel_launch(void* const* d_in, const int* in_sizes, int n_in,
                              void* d_out, int out_size)
{
    const float* hidden = (const float*)d_in[0];
    const float* rela   = (const float*)d_in[1];
    const int*   nei    = (const int*)  d_in[3];
    const float* W      = (const float*)d_in[4];
    const float* b      = (const float*)d_in[5];
    float*       out    = (float*)d_out;

    precompute_kernel<<<P / 8, 256>>>(hidden, W, out);
    scores_softmax_kernel<<<P, NTHR>>>(rela, nei, W, b);
    hsum_kernel<<<NIT * NJT, NTHR>>>(hidden, out);
}

// round 10
// speedup vs baseline: 2.4776x; 1.0804x over previous
#include <cuda_runtime.h>
#include <cuda_bf16.h>

// Problem constants (match setup_inputs: P=1024, M=64, R=64)
#define P 1024
#define MDIM 64
#define RDIM 64
#define NTHR 256
#define PF 2       // software-pipeline depth (float4 buffers in flight)

// hsum tiling
#define ITILE 16
#define JTILE 128
#define NJT   (P / JTILE)   // 8
#define NIT   (P / ITILE)   // 64

// Allocation-free scratch (__device__ globals)
__device__ float g_hi[P];
__device__ float g_hj[P];
__device__ float g_attn[P * P];   // 4 MB: final masked+normalized attention

// ---------------------------------------------------------------------------
// Kernel 1: hi[i] = dot(H[i], W[64:128]), hj[i] = dot(H[i], W[128:192])
// Also zero-initializes d_out (65536 floats) so hsum can use atomicAdd.
// ---------------------------------------------------------------------------
__global__ __launch_bounds__(256) void precompute_kernel(
    const float* __restrict__ hidden, const float* __restrict__ W,
    float* __restrict__ out)
{
    int warp = threadIdx.x >> 5;
    int lane = threadIdx.x & 31;
    int row  = blockIdx.x * 8 + warp;
    int gid  = blockIdx.x * 256 + threadIdx.x;   // 32768 threads

    // zero d_out: 65536 floats = 32768 float2
    reinterpret_cast<float2*>(out)[gid] = make_float2(0.0f, 0.0f);

    float2 h = reinterpret_cast<const float2*>(hidden + (size_t)row * MDIM)[lane];
    float wi0 = W[RDIM + lane * 2];
    float wi1 = W[RDIM + lane * 2 + 1];
    float wj0 = W[RDIM + MDIM + lane * 2];
    float wj1 = W[RDIM + MDIM + lane * 2 + 1];

    float si = h.x * wi0 + h.y * wi1;
    float sj = h.x * wj0 + h.y * wj1;
    #pragma unroll
    for (int off = 16; off >= 1; off >>= 1) {
        si += __shfl_xor_sync(0xFFFFFFFFu, si, off);
        sj += __shfl_xor_sync(0xFFFFFFFFu, sj, off);
    }
    if (lane == 0) {
        g_hi[row] = si;
        g_hj[row] = sj;
    }
}

// ---------------------------------------------------------------------------
// Kernel 2: one block per row i. Streams 256 KB of rela via __ldcs
// (evict-first: single-use data), depth-2 pipeline, two shfl folds ->
// 4 partials/j in padded smem; finish + softmax + mask; write attn row.
// smem ~25.4 KB, regs capped 32 -> 8 CTA/SM -> 64 warps/SM, single wave.
// ---------------------------------------------------------------------------
__global__ __launch_bounds__(NTHR, 8) void scores_softmax_kernel(
    const float* __restrict__ rela,
    const int*   __restrict__ nei,
    const float* __restrict__ W,
    const float* __restrict__ bptr)
{
    __shared__ float part[P * 5];        // 4 partials per j, padded to 5 (20 KB)
    __shared__ float sc[P];              // pos -> exp (4 KB)
    __shared__ unsigned char smask[P];   // nei>0 (1 KB)
    __shared__ float red[8];

    const int tid  = threadIdx.x;
    const int warp = tid >> 5;
    const int lane = tid & 31;
    const int half = (lane >> 4);
    const int lh   = lane & 15;          // lane within half-warp
    const int hwid = warp * 2 + half;    // 0..15 half-warp id

    const int i = blockIdx.x;

    {
        int4 n4 = reinterpret_cast<const int4*>(nei + (size_t)i * P)[tid];
        unsigned int m = (n4.x > 0 ? 1u : 0u) | (n4.y > 0 ? 0x100u : 0u)
                       | (n4.z > 0 ? 0x10000u : 0u) | (n4.w > 0 ? 0x1000000u : 0u);
        reinterpret_cast<unsigned int*>(smask)[tid] = m;
    }
    __syncthreads();

    // ---- Phase 1: stream rela row i; 2 shfl folds -> 4 partials per j ----
    {
        const float4 wv = __ldg(&reinterpret_cast<const float4*>(W)[lh]);
        // iteration k handles j = k*16 + hwid; this thread reads float4 #lh of j
        const float4* p = reinterpret_cast<const float4*>(rela + (size_t)i * (P * RDIM))
                        + (size_t)hwid * 16 + lh;
        // stride between consecutive k for this thread: 16 j's * 16 float4 = 256
        float4 buf[PF];
        #pragma unroll
        for (int q = 0; q < PF; q++) buf[q] = __ldcs(p + q * 256);
        p += PF * 256;

        #pragma unroll 8
        for (int kk = 0; kk < 64 / PF; kk++) {
            #pragma unroll
            for (int q = 0; q < PF; q++) {
                float4 v = buf[q];
                if (kk < 64 / PF - 1) buf[q] = __ldcs(p + q * 256);  // prefetch k+PF
                float s = fmaf(v.x, wv.x, fmaf(v.y, wv.y, fmaf(v.z, wv.z, v.w * wv.w)));
                s += __shfl_xor_sync(0xFFFFFFFFu, s, 8);     // 16 -> 8
                s += __shfl_xor_sync(0xFFFFFFFFu, s, 4);     // 8 -> 4 partials
                const int j = (kk * PF + q) * 16 + hwid;
                if (lh < 4) part[j * 5 + lh] = s;            // conflict-free (pad 5)
            }
            p += PF * 256;
        }
    }
    const float b   = bptr[0];
    const float hii = g_hi[i];
    __syncthreads();

    // ---- Phase 2a: finish dots + bias + mask + "Pos", fused with max-pass ----
    float mx = -1e30f;
    #pragma unroll
    for (int q = 0; q < P / NTHR; q++) {
        const int j = q * NTHR + tid;            // lane stride 5 floats: conflict-free
        const float* pj = &part[j * 5];
        float s = (pj[0] + pj[1]) + (pj[2] + pj[3]);
        s += hii + g_hj[j] + b;                  // g_hj: coalesced L2 hit
        float pos = smask[j] ? s : 0.0f;
        if (pos == 0.0f) pos = -1e-6f;
        sc[j] = pos;
        mx = fmaxf(mx, pos);
    }
    #pragma unroll
    for (int off = 16; off >= 1; off >>= 1)
        mx = fmaxf(mx, __shfl_xor_sync(0xFFFFFFFFu, mx, off));
    if (lane == 0) red[warp] = mx;
    __syncthreads();
    {
        float m = red[0];
        #pragma unroll
        for (int w = 1; w < 8; w++) m = fmaxf(m, red[w]);
        mx = m;
    }
    __syncthreads();

    // ---- Phase 2b: exp + sum ----
    float sum = 0.0f;
    #pragma unroll
    for (int q = 0; q < P / NTHR; q++) {
        int j = q * NTHR + tid;
        float e = __expf(sc[j] - mx);
        sc[j] = e;
        sum += e;
    }
    #pragma unroll
    for (int off = 16; off >= 1; off >>= 1)
        sum += __shfl_xor_sync(0xFFFFFFFFu, sum, off);
    if (lane == 0) red[warp] = sum;
    __syncthreads();
    float inv;
    {
        float s = 0.0f;
        #pragma unroll
        for (int w = 0; w < 8; w++) s += red[w];
        inv = 1.0f / s;
    }

    // ---- write final attn row (masked, normalized) as float4 ----
    {
        float4 a;
        int j0 = tid * 4;
        a.x = smask[j0 + 0] ? sc[j0 + 0] * inv : 0.0f;
        a.y = smask[j0 + 1] ? sc[j0 + 1] * inv : 0.0f;
        a.z = smask[j0 + 2] ? sc[j0 + 2] * inv : 0.0f;
        a.w = smask[j0 + 3] ? sc[j0 + 3] * inv : 0.0f;
        reinterpret_cast<float4*>(g_attn + (size_t)i * P)[tid] = a;
    }
}

// ---------------------------------------------------------------------------
// Kernel 3: H_sum = attn @ hidden, tiled: 64 i-tiles (16 rows) x 8 j-tiles
// (128 j) = 512 blocks. attn tile in smem, 16 accumulators/thread,
// jg-reduce in smem, atomicAdd to out (8 contributions per element).
// ---------------------------------------------------------------------------
__global__ __launch_bounds__(NTHR) void hsum_kernel(
    const float* __restrict__ hidden,
    float*       __restrict__ out)
{
    __shared__ float sat[ITILE][JTILE];          // 8 KB
    __shared__ float partb[4][ITILE][MDIM];      // 16 KB

    const int tid = threadIdx.x;
    const int it  = blockIdx.x >> 3;         // 0..63
    const int jt  = blockIdx.x & 7;          // 0..7
    const int i0  = it * ITILE;
    const int j0  = jt * JTILE;

    // stage attn tile: 512 float4, 2 per thread, coalesced
    #pragma unroll
    for (int t = tid; t < ITILE * JTILE / 4; t += NTHR) {
        int r  = t >> 5;                      // 32 float4 per row
        int c4 = t & 31;
        reinterpret_cast<float4*>(sat[r])[c4] =
            reinterpret_cast<const float4*>(g_attn + (size_t)(i0 + r) * P + j0)[c4];
    }
    __syncthreads();

    const int d  = tid & (MDIM - 1);
    const int jg = tid >> 6;                  // 0..3, 32 j's each
    float acc[ITILE];
    #pragma unroll
    for (int r = 0; r < ITILE; r++) acc[r] = 0.0f;

    #pragma unroll 4
    for (int jj = 0; jj < JTILE / 4; jj++) {
        int j = jg * (JTILE / 4) + jj;
        float h = __ldg(&hidden[(size_t)(j0 + j) * MDIM + d]);  // coalesced, L2/L1 hits
        #pragma unroll
        for (int r = 0; r < ITILE; r++) acc[r] = fmaf(sat[r][j], h, acc[r]);
    }
    #pragma unroll
    for (int r = 0; r < ITILE; r++) partb[jg][r][d] = acc[r];
    __syncthreads();

    // each thread finalizes 4 (r,d) outputs
    #pragma unroll
    for (int rr = 0; rr < 4; rr++) {
        int r = rr * 4 + jg;
        float v = partb[0][r][d] + partb[1][r][d] + partb[2][r][d] + partb[3][r][d];
        atomicAdd(&out[(size_t)(i0 + r) * MDIM + d], v);
    }
}

// ---------------------------------------------------------------------------
// Inputs (metadata order): 0 hidden_state f32[1024,64], 1 rela_state f32[1024,1024,64],
// 2 corr_index f32 (UNUSED), 3 nei_index i32[1024,1024], 4 W f32[192], 5 b f32[1].
// Output: f32[1024,64].
// ---------------------------------------------------------------------------
extern "C" void kernel_launch(void* const* d_in, const int* in_sizes, int n_in,
                              void* d_out, int out_size)
{
    const float* hidden = (const float*)d_in[0];
    const float* rela   = (const float*)d_in[1];
    const int*   nei    = (const int*)  d_in[3];
    const float* W      = (const float*)d_in[4];
    const float* b      = (const float*)d_in[5];
    float*       out    = (float*)d_out;

    precompute_kernel<<<P / 8, 256>>>(hidden, W, out);
    scores_softmax_kernel<<<P, NTHR>>>(rela, nei, W, b);
    hsum_kernel<<<NIT * NJT, NTHR>>>(hidden, out);
}

// round 11
// speedup vs baseline: 2.7033x; 1.0911x over previous
#include <cuda_runtime.h>
#include <cuda_bf16.h>

// Problem constants (match setup_inputs: P=1024, M=64, R=64)
#define P 1024
#define MDIM 64
#define RDIM 64
#define NTHR 256
#define PF 2       // software-pipeline depth (float4 buffers in flight)
#define QJ  256    // j's per stream block (quarter row)

// hsum tiling
#define ITILE 16
#define JTILE 128
#define NJT   (P / JTILE)   // 8
#define NIT   (P / ITILE)   // 64

// Allocation-free scratch (__device__ globals)
__device__ float g_hi[P];
__device__ float g_hj[P];
__device__ float g_attn[P * P];   // 4 MB: Pos scores, then (in place) attn

// ---------------------------------------------------------------------------
// Kernel 1: hi[i] = dot(H[i], W[64:128]), hj[i] = dot(H[i], W[128:192])
// Also zero-initializes d_out (65536 floats) so hsum can use atomicAdd.
// ---------------------------------------------------------------------------
__global__ __launch_bounds__(256) void precompute_kernel(
    const float* __restrict__ hidden, const float* __restrict__ W,
    float* __restrict__ out)
{
    int warp = threadIdx.x >> 5;
    int lane = threadIdx.x & 31;
    int row  = blockIdx.x * 8 + warp;
    int gid  = blockIdx.x * 256 + threadIdx.x;   // 32768 threads

    // zero d_out: 65536 floats = 32768 float2
    reinterpret_cast<float2*>(out)[gid] = make_float2(0.0f, 0.0f);

    float2 h = reinterpret_cast<const float2*>(hidden + (size_t)row * MDIM)[lane];
    float wi0 = W[RDIM + lane * 2];
    float wi1 = W[RDIM + lane * 2 + 1];
    float wj0 = W[RDIM + MDIM + lane * 2];
    float wj1 = W[RDIM + MDIM + lane * 2 + 1];

    float si = h.x * wi0 + h.y * wi1;
    float sj = h.x * wj0 + h.y * wj1;
    #pragma unroll
    for (int off = 16; off >= 1; off >>= 1) {
        si += __shfl_xor_sync(0xFFFFFFFFu, si, off);
        sj += __shfl_xor_sync(0xFFFFFFFFu, sj, off);
    }
    if (lane == 0) {
        g_hi[row] = si;
        g_hj[row] = sj;
    }
}

// ---------------------------------------------------------------------------
// Kernel 2a: pure streaming dot. 4096 blocks; block = (row i, quarter q):
// streams 64 KB of rela via __ldcs, produces 256 finished "Pos" values.
// Fine granularity -> CLC work-steal backfill smooths the wave tail.
// smem ~5 KB -> warp-limited occupancy (8 CTA/SM).
// ---------------------------------------------------------------------------
__global__ __launch_bounds__(NTHR, 8) void stream_scores_kernel(
    const float* __restrict__ rela,
    const int*   __restrict__ nei,
    const float* __restrict__ W,
    const float* __restrict__ bptr)
{
    __shared__ float part[QJ * 5];       // 4 partials per local j, padded (5 KB)

    const int tid  = threadIdx.x;
    const int warp = tid >> 5;
    const int lane = tid & 31;
    const int half = (lane >> 4);
    const int lh   = lane & 15;          // lane within half-warp
    const int hwid = warp * 2 + half;    // 0..15 half-warp id

    const int i  = blockIdx.x >> 2;
    const int q  = blockIdx.x & 3;
    const int j0 = q * QJ;

    // ---- stream 64 KB: 16 iterations x 16 j's ----
    {
        const float4 wv = __ldg(&reinterpret_cast<const float4*>(W)[lh]);
        // iteration k handles local j = k*16 + hwid; this thread reads float4 #lh
        const float4* p = reinterpret_cast<const float4*>(rela + (size_t)i * (P * RDIM))
                        + (size_t)(j0 + hwid) * 16 + lh;
        // stride per k: 16 j's * 16 float4 = 256 float4
        float4 buf[PF];
        #pragma unroll
        for (int qq = 0; qq < PF; qq++) buf[qq] = __ldcs(p + qq * 256);
        p += PF * 256;

        #pragma unroll
        for (int kk = 0; kk < (QJ / 16) / PF; kk++) {
            #pragma unroll
            for (int qq = 0; qq < PF; qq++) {
                float4 v = buf[qq];
                if (kk < (QJ / 16) / PF - 1) buf[qq] = __ldcs(p + qq * 256);
                float s = fmaf(v.x, wv.x, fmaf(v.y, wv.y, fmaf(v.z, wv.z, v.w * wv.w)));
                s += __shfl_xor_sync(0xFFFFFFFFu, s, 8);     // 16 -> 8
                s += __shfl_xor_sync(0xFFFFFFFFu, s, 4);     // 8 -> 4 partials
                const int jl = (kk * PF + qq) * 16 + hwid;
                if (lh < 4) part[jl * 5 + lh] = s;           // conflict-free (pad 5)
            }
            p += PF * 256;
        }
    }
    __syncthreads();

    // ---- finish: thread tid <-> local j = tid ----
    {
        const int j = j0 + tid;
        const float* pj = &part[tid * 5];          // stride 5: conflict-free
        float s = (pj[0] + pj[1]) + (pj[2] + pj[3]);
        s += g_hi[i] + g_hj[j] + bptr[0];
        bool m = nei[(size_t)i * P + j] > 0;       // coalesced 1 KB
        float pos = m ? s : 0.0f;
        if (pos == 0.0f) pos = -1e-6f;
        g_attn[(size_t)i * P + j] = pos;           // coalesced 1 KB
    }
}

// ---------------------------------------------------------------------------
// Kernel 2b: per-row softmax + re-mask, IN PLACE over g_attn.
// 1024 blocks x 256 threads; each thread owns 4 contiguous j (float4),
// values carried in registers between passes -> in-place is safe.
// ---------------------------------------------------------------------------
__global__ __launch_bounds__(NTHR) void softmax_kernel(
    const int* __restrict__ nei)
{
    __shared__ float red[8];

    const int tid  = threadIdx.x;
    const int warp = tid >> 5;
    const int lane = tid & 31;
    const int i    = blockIdx.x;

    float4 v = reinterpret_cast<const float4*>(g_attn + (size_t)i * P)[tid];

    // max
    float mx = fmaxf(fmaxf(v.x, v.y), fmaxf(v.z, v.w));
    #pragma unroll
    for (int off = 16; off >= 1; off >>= 1)
        mx = fmaxf(mx, __shfl_xor_sync(0xFFFFFFFFu, mx, off));
    if (lane == 0) red[warp] = mx;
    __syncthreads();
    {
        float m = red[0];
        #pragma unroll
        for (int w = 1; w < 8; w++) m = fmaxf(m, red[w]);
        mx = m;
    }
    __syncthreads();

    // exp + sum
    v.x = __expf(v.x - mx);
    v.y = __expf(v.y - mx);
    v.z = __expf(v.z - mx);
    v.w = __expf(v.w - mx);
    float sum = (v.x + v.y) + (v.z + v.w);
    #pragma unroll
    for (int off = 16; off >= 1; off >>= 1)
        sum += __shfl_xor_sync(0xFFFFFFFFu, sum, off);
    if (lane == 0) red[warp] = sum;
    __syncthreads();
    float inv;
    {
        float s = 0.0f;
        #pragma unroll
        for (int w = 0; w < 8; w++) s += red[w];
        inv = 1.0f / s;
    }

    // re-mask + normalize, write back in place
    int4 n4 = reinterpret_cast<const int4*>(nei + (size_t)i * P)[tid];
    float4 a;
    a.x = (n4.x > 0) ? v.x * inv : 0.0f;
    a.y = (n4.y > 0) ? v.y * inv : 0.0f;
    a.z = (n4.z > 0) ? v.z * inv : 0.0f;
    a.w = (n4.w > 0) ? v.w * inv : 0.0f;
    reinterpret_cast<float4*>(g_attn + (size_t)i * P)[tid] = a;
}

// ---------------------------------------------------------------------------
// Kernel 3: H_sum = attn @ hidden, tiled: 64 i-tiles x 8 j-tiles = 512 blocks.
// attn tile in smem, 16 accumulators/thread, jg-reduce in smem, atomicAdd out.
// ---------------------------------------------------------------------------
__global__ __launch_bounds__(NTHR) void hsum_kernel(
    const float* __restrict__ hidden,
    float*       __restrict__ out)
{
    __shared__ float sat[ITILE][JTILE];          // 8 KB
    __shared__ float partb[4][ITILE][MDIM];      // 16 KB

    const int tid = threadIdx.x;
    const int it  = blockIdx.x >> 3;         // 0..63
    const int jt  = blockIdx.x & 7;          // 0..7
    const int i0  = it * ITILE;
    const int j0  = jt * JTILE;

    // stage attn tile: 512 float4, 2 per thread, coalesced
    #pragma unroll
    for (int t = tid; t < ITILE * JTILE / 4; t += NTHR) {
        int r  = t >> 5;                      // 32 float4 per row
        int c4 = t & 31;
        reinterpret_cast<float4*>(sat[r])[c4] =
            reinterpret_cast<const float4*>(g_attn + (size_t)(i0 + r) * P + j0)[c4];
    }
    __syncthreads();

    const int d  = tid & (MDIM - 1);
    const int jg = tid >> 6;                  // 0..3, 32 j's each
    float acc[ITILE];
    #pragma unroll
    for (int r = 0; r < ITILE; r++) acc[r] = 0.0f;

    #pragma unroll 4
    for (int jj = 0; jj < JTILE / 4; jj++) {
        int j = jg * (JTILE / 4) + jj;
        float h = __ldg(&hidden[(size_t)(j0 + j) * MDIM + d]);  // coalesced, L2/L1 hits
        #pragma unroll
        for (int r = 0; r < ITILE; r++) acc[r] = fmaf(sat[r][j], h, acc[r]);
    }
    #pragma unroll
    for (int r = 0; r < ITILE; r++) partb[jg][r][d] = acc[r];
    __syncthreads();

    // each thread finalizes 4 (r,d) outputs
    #pragma unroll
    for (int rr = 0; rr < 4; rr++) {
        int r = rr * 4 + jg;
        float v = partb[0][r][d] + partb[1][r][d] + partb[2][r][d] + partb[3][r][d];
        atomicAdd(&out[(size_t)(i0 + r) * MDIM + d], v);
    }
}

// ---------------------------------------------------------------------------
// Inputs (metadata order): 0 hidden_state f32[1024,64], 1 rela_state f32[1024,1024,64],
// 2 corr_index f32 (UNUSED), 3 nei_index i32[1024,1024], 4 W f32[192], 5 b f32[1].
// Output: f32[1024,64].
// ---------------------------------------------------------------------------
extern "C" void kernel_launch(void* const* d_in, const int* in_sizes, int n_in,
                              void* d_out, int out_size)
{
    const float* hidden = (const float*)d_in[0];
    const float* rela   = (const float*)d_in[1];
    const int*   nei    = (const int*)  d_in[3];
    const float* W      = (const float*)d_in[4];
    const float* b      = (const float*)d_in[5];
    float*       out    = (float*)d_out;

    precompute_kernel<<<P / 8, 256>>>(hidden, W, out);
    stream_scores_kernel<<<P * 4, NTHR>>>(rela, nei, W, b);
    softmax_kernel<<<P, NTHR>>>(nei);
    hsum_kernel<<<NIT * NJT, NTHR>>>(hidden, out);
}

// round 12
// speedup vs baseline: 2.8111x; 1.0399x over previous
#include <cuda_runtime.h>
#include <cuda_bf16.h>

// Problem constants (match setup_inputs: P=1024, M=64, R=64)
#define P 1024
#define MDIM 64
#define RDIM 64
#define NTHR 256
#define PF 2       // software-pipeline depth (float4 buffers in flight)
#define QJ  256    // j's per stream block (quarter row)
#define NSTREAM (P * 4)   // 4096 stream blocks
#define NPRE    (P / 8)   // 128 precompute blocks appended to the same grid

// hsum tiling
#define ITILE 8
#define JTILE 128
#define NJT   (P / JTILE)   // 8
#define NIT   (P / ITILE)   // 128

// Allocation-free scratch (__device__ globals)
__device__ float g_hi[P];
__device__ float g_hj[P];
__device__ float g_attn[P * P];   // 4 MB: raw dots -> (in place) attn

// ---------------------------------------------------------------------------
// Kernel A: combined grid.
//   blocks [0, 4096): block = (row i, quarter q); streams 64 KB of rela via
//     __ldcs and writes 256 RAW dot values (rela . Wr) to g_attn.
//   blocks [4096, 4224): precompute hi/hj (warp-per-row dots) + zero d_out.
//   No ordering needed between the two groups (raw dots don't use hi/hj).
// ---------------------------------------------------------------------------
__global__ __launch_bounds__(NTHR, 8) void stream_scores_kernel(
    const float* __restrict__ rela,
    const float* __restrict__ hidden,
    const float* __restrict__ W,
    float* __restrict__ out)
{
    const int tid  = threadIdx.x;
    const int warp = tid >> 5;
    const int lane = tid & 31;

    if (blockIdx.x >= NSTREAM) {
        // ---- precompute branch: hi/hj + zero d_out ----
        const int pid = blockIdx.x - NSTREAM;        // 0..127
        const int row = pid * 8 + warp;
        const int gid = pid * 256 + tid;             // 32768 threads

        reinterpret_cast<float2*>(out)[gid] = make_float2(0.0f, 0.0f);

        float2 h = reinterpret_cast<const float2*>(hidden + (size_t)row * MDIM)[lane];
        float wi0 = W[RDIM + lane * 2];
        float wi1 = W[RDIM + lane * 2 + 1];
        float wj0 = W[RDIM + MDIM + lane * 2];
        float wj1 = W[RDIM + MDIM + lane * 2 + 1];

        float si = h.x * wi0 + h.y * wi1;
        float sj = h.x * wj0 + h.y * wj1;
        #pragma unroll
        for (int off = 16; off >= 1; off >>= 1) {
            si += __shfl_xor_sync(0xFFFFFFFFu, si, off);
            sj += __shfl_xor_sync(0xFFFFFFFFu, sj, off);
        }
        if (lane == 0) {
            g_hi[row] = si;
            g_hj[row] = sj;
        }
        return;
    }

    // ---- streaming branch ----
    __shared__ float part[QJ * 5];       // 4 partials per local j, padded (5 KB)

    const int half = (lane >> 4);
    const int lh   = lane & 15;          // lane within half-warp
    const int hwid = warp * 2 + half;    // 0..15 half-warp id

    const int i  = blockIdx.x >> 2;
    const int q  = blockIdx.x & 3;
    const int j0 = q * QJ;

    {
        const float4 wv = __ldg(&reinterpret_cast<const float4*>(W)[lh]);
        // iteration k handles local j = k*16 + hwid; this thread reads float4 #lh
        const float4* p = reinterpret_cast<const float4*>(rela + (size_t)i * (P * RDIM))
                        + (size_t)(j0 + hwid) * 16 + lh;
        // stride per k: 16 j's * 16 float4 = 256 float4
        float4 buf[PF];
        #pragma unroll
        for (int qq = 0; qq < PF; qq++) buf[qq] = __ldcs(p + qq * 256);
        p += PF * 256;

        #pragma unroll
        for (int kk = 0; kk < (QJ / 16) / PF; kk++) {
            #pragma unroll
            for (int qq = 0; qq < PF; qq++) {
                float4 v = buf[qq];
                if (kk < (QJ / 16) / PF - 1) buf[qq] = __ldcs(p + qq * 256);
                float s = fmaf(v.x, wv.x, fmaf(v.y, wv.y, fmaf(v.z, wv.z, v.w * wv.w)));
                s += __shfl_xor_sync(0xFFFFFFFFu, s, 8);     // 16 -> 8
                s += __shfl_xor_sync(0xFFFFFFFFu, s, 4);     // 8 -> 4 partials
                const int jl = (kk * PF + qq) * 16 + hwid;
                if (lh < 4) part[jl * 5 + lh] = s;           // conflict-free (pad 5)
            }
            p += PF * 256;
        }
    }
    __syncthreads();

    // ---- finish: thread tid <-> local j = tid; write RAW dot ----
    {
        const float* pj = &part[tid * 5];          // stride 5: conflict-free
        float s = (pj[0] + pj[1]) + (pj[2] + pj[3]);
        g_attn[(size_t)i * P + j0 + tid] = s;      // coalesced 1 KB
    }
}

// ---------------------------------------------------------------------------
// Kernel B: per-row bias-add + mask + softmax + re-mask, IN PLACE over g_attn.
// 1024 blocks x 256 threads; each thread owns 4 contiguous j (float4),
// values carried in registers between passes -> in-place is safe.
// ---------------------------------------------------------------------------
__global__ __launch_bounds__(NTHR) void softmax_kernel(
    const int* __restrict__ nei,
    const float* __restrict__ bptr)
{
    __shared__ float red[8];

    const int tid  = threadIdx.x;
    const int warp = tid >> 5;
    const int lane = tid & 31;
    const int i    = blockIdx.x;

    float4 v = reinterpret_cast<const float4*>(g_attn + (size_t)i * P)[tid];
    int4  n4 = reinterpret_cast<const int4*>(nei + (size_t)i * P)[tid];
    float4 hj = reinterpret_cast<const float4*>(g_hj)[tid];
    const float hb = g_hi[i] + bptr[0];

    // finish scores -> "Pos"
    v.x = (n4.x > 0) ? (v.x + hj.x + hb) : 0.0f;  if (v.x == 0.0f) v.x = -1e-6f;
    v.y = (n4.y > 0) ? (v.y + hj.y + hb) : 0.0f;  if (v.y == 0.0f) v.y = -1e-6f;
    v.z = (n4.z > 0) ? (v.z + hj.z + hb) : 0.0f;  if (v.z == 0.0f) v.z = -1e-6f;
    v.w = (n4.w > 0) ? (v.w + hj.w + hb) : 0.0f;  if (v.w == 0.0f) v.w = -1e-6f;

    // max
    float mx = fmaxf(fmaxf(v.x, v.y), fmaxf(v.z, v.w));
    #pragma unroll
    for (int off = 16; off >= 1; off >>= 1)
        mx = fmaxf(mx, __shfl_xor_sync(0xFFFFFFFFu, mx, off));
    if (lane == 0) red[warp] = mx;
    __syncthreads();
    {
        float m = red[0];
        #pragma unroll
        for (int w = 1; w < 8; w++) m = fmaxf(m, red[w]);
        mx = m;
    }
    __syncthreads();

    // exp + sum
    v.x = __expf(v.x - mx);
    v.y = __expf(v.y - mx);
    v.z = __expf(v.z - mx);
    v.w = __expf(v.w - mx);
    float sum = (v.x + v.y) + (v.z + v.w);
    #pragma unroll
    for (int off = 16; off >= 1; off >>= 1)
        sum += __shfl_xor_sync(0xFFFFFFFFu, sum, off);
    if (lane == 0) red[warp] = sum;
    __syncthreads();
    float inv;
    {
        float s = 0.0f;
        #pragma unroll
        for (int w = 0; w < 8; w++) s += red[w];
        inv = 1.0f / s;
    }

    // re-mask + normalize, write back in place
    float4 a;
    a.x = (n4.x > 0) ? v.x * inv : 0.0f;
    a.y = (n4.y > 0) ? v.y * inv : 0.0f;
    a.z = (n4.z > 0) ? v.z * inv : 0.0f;
    a.w = (n4.w > 0) ? v.w * inv : 0.0f;
    reinterpret_cast<float4*>(g_attn + (size_t)i * P)[tid] = a;
}

// ---------------------------------------------------------------------------
// Kernel C: H_sum = attn @ hidden, tiled: 128 i-tiles (8 rows) x 8 j-tiles
// (128 j) = 1024 blocks. 8 accumulators/thread keeps regs ~50 -> high occ.
// ---------------------------------------------------------------------------
__global__ __launch_bounds__(NTHR) void hsum_kernel(
    const float* __restrict__ hidden,
    float*       __restrict__ out)
{
    __shared__ float sat[ITILE][JTILE];          // 4 KB
    __shared__ float partb[4][ITILE][MDIM];      // 8 KB

    const int tid = threadIdx.x;
    const int it  = blockIdx.x >> 3;          // 0..127
    const int jt  = blockIdx.x & 7;           // 0..7
    const int i0  = it * ITILE;
    const int j0  = jt * JTILE;

    // stage attn tile: 256 float4, 1 per thread, coalesced
    {
        int r  = tid >> 5;                     // 32 float4 per row
        int c4 = tid & 31;
        reinterpret_cast<float4*>(sat[r])[c4] =
            reinterpret_cast<const float4*>(g_attn + (size_t)(i0 + r) * P + j0)[c4];
    }
    __syncthreads();

    const int d  = tid & (MDIM - 1);
    const int jg = tid >> 6;                   // 0..3, 32 j's each
    float acc[ITILE];
    #pragma unroll
    for (int r = 0; r < ITILE; r++) acc[r] = 0.0f;

    #pragma unroll 8
    for (int jj = 0; jj < JTILE / 4; jj++) {
        int j = jg * (JTILE / 4) + jj;
        float h = __ldg(&hidden[(size_t)(j0 + j) * MDIM + d]);  // coalesced, L1/L2 hits
        #pragma unroll
        for (int r = 0; r < ITILE; r++) acc[r] = fmaf(sat[r][j], h, acc[r]);
    }
    #pragma unroll
    for (int r = 0; r < ITILE; r++) partb[jg][r][d] = acc[r];
    __syncthreads();

    // each thread finalizes 2 (r,d) outputs
    #pragma unroll
    for (int rr = 0; rr < 2; rr++) {
        int r = rr * 4 + jg;
        float v = partb[0][r][d] + partb[1][r][d] + partb[2][r][d] + partb[3][r][d];
        atomicAdd(&out[(size_t)(i0 + r) * MDIM + d], v);
    }
}

// ---------------------------------------------------------------------------
// Inputs (metadata order): 0 hidden_state f32[1024,64], 1 rela_state f32[1024,1024,64],
// 2 corr_index f32 (UNUSED), 3 nei_index i32[1024,1024], 4 W f32[192], 5 b f32[1].
// Output: f32[1024,64].
// ---------------------------------------------------------------------------
extern "C" void kernel_launch(void* const* d_in, const int* in_sizes, int n_in,
                              void* d_out, int out_size)
{
    const float* hidden = (const float*)d_in[0];
    const float* rela   = (const float*)d_in[1];
    const int*   nei    = (const int*)  d_in[3];
    const float* W      = (const float*)d_in[4];
    const float* b      = (const float*)d_in[5];
    float*       out    = (float*)d_out;

    stream_scores_kernel<<<NSTREAM + NPRE, NTHR>>>(rela, hidden, W, out);
    softmax_kernel<<<P, NTHR>>>(nei, b);
    hsum_kernel<<<NIT * NJT, NTHR>>>(hidden, out);
}